// round 13
// baseline (speedup 1.0000x reference)
#include <cuda_runtime.h>
#include <cuda_fp16.h>
#include <cstdint>

#define D      128
#define DM     1024
#define BATCH  4
#define SEQ    4096
#define ROWS   (BATCH * SEQ)   // 16384
#define TSPL   16              // ktv split count
#define NCH2   16              // qkv K chunks of 64

// Scratch (allocation-free rule: __device__ globals)
__device__ __half g_xh[(size_t)ROWS * DM];
__device__ __half g_wh[3 * D * DM];
__device__ __half g_qh[ROWS * D];
__device__ __half g_kh[ROWS * D];
__device__ __half g_vh[ROWS * D];
__device__ float  g_mpart[BATCH * TSPL * D * D];
__device__ __half g_mh[BATCH * D * D];

// ===========================================================================
// helpers (sm_80-era PTX: ldmatrix / mma.sync / cp.async)
// ===========================================================================
__device__ __forceinline__ uint32_t s2u(const void* p) {
    uint32_t a;
    asm("{ .reg .u64 t; cvta.to.shared.u64 t, %1; cvt.u32.u64 %0, t; }"
        : "=r"(a) : "l"(p));
    return a;
}
__device__ __forceinline__ void ldsm4(uint32_t* r, uint32_t addr) {
    asm volatile("ldmatrix.sync.aligned.m8n8.x4.shared.b16 {%0,%1,%2,%3}, [%4];"
                 : "=r"(r[0]), "=r"(r[1]), "=r"(r[2]), "=r"(r[3]) : "r"(addr));
}
__device__ __forceinline__ void ldsm4t(uint32_t* r, uint32_t addr) {
    asm volatile("ldmatrix.sync.aligned.m8n8.x4.trans.shared.b16 {%0,%1,%2,%3}, [%4];"
                 : "=r"(r[0]), "=r"(r[1]), "=r"(r[2]), "=r"(r[3]) : "r"(addr));
}
__device__ __forceinline__ void mma_fp16(float* d, const uint32_t* a,
                                         uint32_t b0, uint32_t b1) {
    asm volatile(
        "mma.sync.aligned.m16n8k16.row.col.f32.f16.f16.f32 "
        "{%0,%1,%2,%3}, {%4,%5,%6,%7}, {%8,%9}, {%0,%1,%2,%3};"
        : "+f"(d[0]), "+f"(d[1]), "+f"(d[2]), "+f"(d[3])
        : "r"(a[0]), "r"(a[1]), "r"(a[2]), "r"(a[3]), "r"(b0), "r"(b1));
}
__device__ __forceinline__ void cpa16(uint32_t dst, const void* src) {
    asm volatile("cp.async.cg.shared.global [%0], [%1], 16;" :: "r"(dst), "l"(src));
}
__device__ __forceinline__ uint32_t pk2(float a, float b) {
    __half2 h = __floats2half2_rn(a, b);
    return *(uint32_t*)&h;
}

// ===========================================================================
// Kernel 0a: convert W -> fp16 (tiny: 384 blocks).
// ===========================================================================
__global__ __launch_bounds__(256) void cvt_w_kernel(
    const float* __restrict__ Wq, const float* __restrict__ Wk,
    const float* __restrict__ Wv)
{
    size_t j = ((size_t)blockIdx.x * 256 + threadIdx.x) * 4;
    if (j >= (size_t)3 * D * DM) return;
    size_t w = j >> 17;
    const float* src = (w == 0) ? Wq : (w == 1) ? Wk : Wv;
    size_t off = j & 131071;
    float4 v = *(const float4*)&src[off];
    *(uint32_t*)&g_wh[j]     = pk2(v.x, v.y);
    *(uint32_t*)&g_wh[j + 2] = pk2(v.z, v.w);
}

// ===========================================================================
// Kernel 0b: convert half of x -> fp16 (8192 blocks per half; full HBM BW).
// ===========================================================================
__global__ __launch_bounds__(256) void cvt_x_kernel(
    const float* __restrict__ x, int half)
{
    size_t i4 = ((size_t)half * 8192 * 256 +
                 (size_t)blockIdx.x * 256 + threadIdx.x) * 4;
    float4 v = *(const float4*)&x[i4];
    *(uint32_t*)&g_xh[i4]     = pk2(v.x, v.y);
    *(uint32_t*)&g_xh[i4 + 2] = pk2(v.z, v.w);
}

// ===========================================================================
// Kernel 1: QKV projection, 1-term fp16 mma. head = head0 + blockIdx.y,
// rows start at rowbase. CTA 128x128xK64 double buffered. fp16-hi out.
// ===========================================================================
#define TS2   144                 // smem bytes per row (128 data + 16 pad)
#define TILE2 (128 * TS2)         // 18432
#define STG2  (2 * TILE2)         // 36864 per stage (Ah, Bh)

__global__ __launch_bounds__(256, 2) void qkv_mma_kernel(
    const float* __restrict__ bq, const float* __restrict__ bk,
    const float* __restrict__ bv, int head0, int rowbase)
{
    extern __shared__ char smem[];
    const uint32_t sb = s2u(smem);

    const int tid  = threadIdx.x;
    const int lane = tid & 31;
    const int wid  = tid >> 5;
    const int wm   = wid & 3;        // 32-row M block
    const int wn   = wid >> 2;       // 64-col N block
    const int head = head0 + blockIdx.y;
    const int row0 = rowbase + blockIdx.x * 128;

    const __half* Ahg = g_xh + (size_t)row0 * DM;
    const __half* Bhg = g_wh + ((size_t)head << 17);
    const float* bias = (head == 0) ? bq : (head == 1) ? bk : bv;
    __half* oh = (head == 0) ? g_qh : (head == 1) ? g_kh : g_vh;

    // cp.async mapping: 128 rows x 8 16B-units = 1024 slots, 4 per thread/tile.
    int cr[4], cu[4];
    #pragma unroll
    for (int i = 0; i < 4; i++) {
        int slot = tid + i * 256;
        cr[i] = slot >> 3;
        cu[i] = slot & 7;
    }

    #define QISSUE(c) do {                                                     \
        uint32_t _b = sb + ((c) & 1) * STG2;                                   \
        _Pragma("unroll")                                                      \
        for (int _i = 0; _i < 4; _i++) {                                       \
            uint32_t _so = (uint32_t)(cr[_i] * TS2 + cu[_i] * 16);             \
            size_t _go = (size_t)cr[_i] * DM + (c) * 64 + cu[_i] * 8;          \
            cpa16(_b + _so,         Ahg + _go);                                \
            cpa16(_b + TILE2 + _so, Bhg + _go);                                \
        }                                                                      \
    } while (0)

    float acc[2][8][4];
    #pragma unroll
    for (int i = 0; i < 2; i++)
        #pragma unroll
        for (int j = 0; j < 8; j++)
            #pragma unroll
            for (int q = 0; q < 4; q++) acc[i][j][q] = 0.0f;

    QISSUE(0);
    asm volatile("cp.async.commit_group;" ::: "memory");
    QISSUE(1);
    asm volatile("cp.async.commit_group;" ::: "memory");

    const uint32_t lrA = (uint32_t)(wm * 32 + (lane & 15));
    const uint32_t lcb = (uint32_t)((lane >> 4) << 4);

    for (int c = 0; c < NCH2; c++) {
        asm volatile("cp.async.wait_group 1;" ::: "memory");
        __syncthreads();

        uint32_t base = sb + (c & 1) * STG2;
        uint32_t aH = base, bH = base + TILE2;

        #pragma unroll
        for (int ks = 0; ks < 4; ks++) {
            uint32_t kb = (uint32_t)(ks * 32) + lcb;
            uint32_t ah[8];
            ldsm4(ah,     aH + lrA * TS2 + kb);
            ldsm4(ah + 4, aH + (lrA + 16) * TS2 + kb);
            #pragma unroll
            for (int nb = 0; nb < 4; nb++) {
                uint32_t rb = (uint32_t)(wn * 64 + nb * 16 + (lane & 15));
                uint32_t bh[4];
                ldsm4(bh, bH + rb * TS2 + kb);
                #pragma unroll
                for (int ma = 0; ma < 2; ma++) {
                    mma_fp16(acc[ma][nb*2+0], ah + ma*4, bh[0], bh[2]);
                    mma_fp16(acc[ma][nb*2+1], ah + ma*4, bh[1], bh[3]);
                }
            }
        }
        __syncthreads();
        if (c + 2 < NCH2) QISSUE(c + 2);
        asm volatile("cp.async.commit_group;" ::: "memory");
    }

    // Epilogue: add bias, store fp16 hi.
    const int g8  = lane >> 2;
    const int t4  = lane & 3;
    #pragma unroll
    for (int ma = 0; ma < 2; ma++) {
        int r = row0 + wm * 32 + ma * 16 + g8;
        #pragma unroll
        for (int na = 0; na < 8; na++) {
            int col = wn * 64 + na * 8 + t4 * 2;
            float bx = __ldg(&bias[col]), by = __ldg(&bias[col + 1]);
            *(uint32_t*)&oh[(size_t)r * D + col] =
                pk2(acc[ma][na][0] + bx, acc[ma][na][1] + by);
            *(uint32_t*)&oh[(size_t)(r + 8) * D + col] =
                pk2(acc[ma][na][2] + bx, acc[ma][na][3] + by);
        }
    }
}

// ===========================================================================
// Kernel 2a: ktv partials on tensor cores, 1-term fp16.
// M_part[d,e] = sum_{t in split} kh[t,d] * vh[t,e]; 256 t-rows per CTA.
// ===========================================================================
#define TS3   272                 // 256 data + 16 pad
#define TILE3 (128 * TS3)         // 34816

__global__ __launch_bounds__(256) void ktv_mma_kernel()
{
    extern __shared__ char smem[];
    const uint32_t sb = s2u(smem);
    const uint32_t sKh = sb, sVh = sb + TILE3;

    const int tid  = threadIdx.x;
    const int lane = tid & 31;
    const int wid  = tid >> 5;
    const int wm   = wid & 3;        // d block (32)
    const int wn   = wid >> 2;       // e block (64)
    const int b    = blockIdx.y;
    const int t0   = blockIdx.x * 256;

    float acc[2][8][4];
    #pragma unroll
    for (int i = 0; i < 2; i++)
        #pragma unroll
        for (int j = 0; j < 8; j++)
            #pragma unroll
            for (int q = 0; q < 4; q++) acc[i][j][q] = 0.0f;

    const uint32_t trow = (uint32_t)(((lane >> 4) & 1) * 8 + (lane & 7));
    const uint32_t tcb  = (uint32_t)(((lane >> 3) & 1) * 16);

    for (int cc = 0; cc < 2; cc++) {
        const __half* khg = g_kh + ((size_t)b * SEQ + t0 + cc * 128) * D;
        const __half* vhg = g_vh + ((size_t)b * SEQ + t0 + cc * 128) * D;

        #pragma unroll
        for (int i = 0; i < 8; i++) {
            int slot = tid + i * 256;          // 2048 slots: 128 rows x 16 units
            int r = slot >> 4, u = slot & 15;
            uint32_t so = (uint32_t)(r * TS3 + u * 16);
            size_t go = (size_t)r * D + u * 8;
            cpa16(sKh + so, khg + go);
            cpa16(sVh + so, vhg + go);
        }
        asm volatile("cp.async.commit_group;" ::: "memory");
        asm volatile("cp.async.wait_group 0;" ::: "memory");
        __syncthreads();

        #pragma unroll
        for (int ks = 0; ks < 8; ks++) {
            uint32_t aoff = ((uint32_t)(ks * 16) + trow) * TS3 + tcb;
            uint32_t ah[8];
            ldsm4t(ah,     sKh + aoff + wm * 64);
            ldsm4t(ah + 4, sKh + aoff + wm * 64 + 32);
            #pragma unroll
            for (int nb = 0; nb < 4; nb++) {
                uint32_t eb = (uint32_t)(wn * 128 + nb * 32);
                uint32_t bh[4];
                ldsm4t(bh, sVh + aoff + eb);
                #pragma unroll
                for (int ma = 0; ma < 2; ma++) {
                    mma_fp16(acc[ma][nb*2+0], ah + ma*4, bh[0], bh[2]);
                    mma_fp16(acc[ma][nb*2+1], ah + ma*4, bh[1], bh[3]);
                }
            }
        }
        __syncthreads();
    }

    float* outp = g_mpart + ((size_t)(b * TSPL + blockIdx.x) << 14);
    const int g8 = lane >> 2;
    const int t4 = lane & 3;
    #pragma unroll
    for (int ma = 0; ma < 2; ma++) {
        int r = wm * 32 + ma * 16 + g8;
        #pragma unroll
        for (int na = 0; na < 8; na++) {
            int col = wn * 64 + na * 8 + t4 * 2;
            *(float2*)&outp[(size_t)r * D + col] =
                make_float2(acc[ma][na][0], acc[ma][na][1]);
            *(float2*)&outp[(size_t)(r + 8) * D + col] =
                make_float2(acc[ma][na][2], acc[ma][na][3]);
        }
    }
}

// ===========================================================================
// Kernel 2b: reduce partials -> Mh fp16 (vectorized float4).
// ===========================================================================
__global__ __launch_bounds__(256) void reduce_m_kernel()
{
    int s  = blockIdx.x * 256 + threadIdx.x;     // 0..16383 (float4 slots)
    int b  = s >> 12;                            // 4096 slots per batch
    int sl = s & 4095;
    const float4* mp4 = (const float4*)g_mpart + ((size_t)b * TSPL << 12);
    float4 sum = make_float4(0.f, 0.f, 0.f, 0.f);
    #pragma unroll
    for (int p = 0; p < TSPL; p++) {
        float4 v = mp4[((size_t)p << 12) + sl];
        sum.x += v.x; sum.y += v.y; sum.z += v.z; sum.w += v.w;
    }
    int idx = s * 4;
    *(uint32_t*)&g_mh[idx]     = pk2(sum.x, sum.y);
    *(uint32_t*)&g_mh[idx + 2] = pk2(sum.z, sum.w);
}

// ===========================================================================
// Kernel 3: out = scale * q @ Mh, 1-term fp16, 64-row Q tiles (256 CTAs).
// A = qh [s][d] (non-trans); B = Mh [d][e] via ldmatrix.trans.
// Warps: 2M x 4N (warp 32x32).
// ===========================================================================
#define QTILE (64 * TS3)          // 17408

__global__ __launch_bounds__(256) void out_mma_kernel(float* __restrict__ out)
{
    extern __shared__ char smem[];
    const uint32_t sb = s2u(smem);
    const uint32_t sQh = sb, sMh = sb + QTILE;

    const int tid  = threadIdx.x;
    const int lane = tid & 31;
    const int wid  = tid >> 5;
    const int wm   = wid & 1;        // s block (32)
    const int wn   = wid >> 1;       // e block (32)
    const int b    = blockIdx.y;
    const int s0   = blockIdx.x * 64;

    const __half* qhg = g_qh + ((size_t)b * SEQ + s0) * D;
    const __half* mhg = g_mh + ((size_t)b << 14);

    #pragma unroll
    for (int i = 0; i < 4; i++) {
        int slot = tid + i * 256;
        int r = slot >> 4, u = slot & 15;
        cpa16(sQh + (uint32_t)(r * TS3 + u * 16), qhg + (size_t)r * D + u * 8);
    }
    #pragma unroll
    for (int i = 0; i < 8; i++) {
        int slot = tid + i * 256;
        int r = slot >> 4, u = slot & 15;
        cpa16(sMh + (uint32_t)(r * TS3 + u * 16), mhg + (size_t)r * D + u * 8);
    }
    asm volatile("cp.async.commit_group;" ::: "memory");
    asm volatile("cp.async.wait_group 0;" ::: "memory");
    __syncthreads();

    float acc[2][4][4];
    #pragma unroll
    for (int i = 0; i < 2; i++)
        #pragma unroll
        for (int j = 0; j < 4; j++)
            #pragma unroll
            for (int q = 0; q < 4; q++) acc[i][j][q] = 0.0f;

    const uint32_t lrA  = (uint32_t)(wm * 32 + (lane & 15));
    const uint32_t lcb  = (uint32_t)((lane >> 4) << 4);
    const uint32_t trow = (uint32_t)(((lane >> 4) & 1) * 8 + (lane & 7));
    const uint32_t tcb  = (uint32_t)(((lane >> 3) & 1) * 16);

    #pragma unroll
    for (int ks = 0; ks < 8; ks++) {
        uint32_t kb = (uint32_t)(ks * 32) + lcb;
        uint32_t ah[8];
        ldsm4(ah,     sQh + lrA * TS3 + kb);
        ldsm4(ah + 4, sQh + (lrA + 16) * TS3 + kb);
        uint32_t boff = ((uint32_t)(ks * 16) + trow) * TS3 + tcb;
        #pragma unroll
        for (int nb = 0; nb < 2; nb++) {
            uint32_t eb = (uint32_t)(wn * 64 + nb * 32);
            uint32_t bh[4];
            ldsm4t(bh, sMh + boff + eb);
            #pragma unroll
            for (int ma = 0; ma < 2; ma++) {
                mma_fp16(acc[ma][nb*2+0], ah + ma*4, bh[0], bh[2]);
                mma_fp16(acc[ma][nb*2+1], ah + ma*4, bh[1], bh[3]);
            }
        }
    }

    const float scale = 0.08838834764831845f;    // 128^-0.5
    const int g8 = lane >> 2;
    const int t4 = lane & 3;
    #pragma unroll
    for (int ma = 0; ma < 2; ma++) {
        int r = s0 + wm * 32 + ma * 16 + g8;
        #pragma unroll
        for (int na = 0; na < 4; na++) {
            int col = wn * 32 + na * 8 + t4 * 2;
            *(float2*)&out[((size_t)b * SEQ + r) * D + col] =
                make_float2(acc[ma][na][0] * scale, acc[ma][na][1] * scale);
            *(float2*)&out[((size_t)b * SEQ + r + 8) * D + col] =
                make_float2(acc[ma][na][2] * scale, acc[ma][na][3] * scale);
        }
    }
}

// ---------------------------------------------------------------------------
extern "C" void kernel_launch(void* const* d_in, const int* in_sizes, int n_in,
                              void* d_out, int out_size)
{
    const float* x  = (const float*)d_in[0];
    const float* Wq = (const float*)d_in[1];
    const float* bq = (const float*)d_in[2];
    const float* Wk = (const float*)d_in[3];
    const float* bk = (const float*)d_in[4];
    const float* Wv = (const float*)d_in[5];
    const float* bv = (const float*)d_in[6];
    float* out = (float*)d_out;

    static cudaStream_t s2 = nullptr;
    static cudaEvent_t evA = nullptr, evB = nullptr, evKV = nullptr, evQ = nullptr;
    if (s2 == nullptr) {
        cudaStreamCreateWithFlags(&s2, cudaStreamNonBlocking);
        cudaEventCreateWithFlags(&evA,  cudaEventDisableTiming);
        cudaEventCreateWithFlags(&evB,  cudaEventDisableTiming);
        cudaEventCreateWithFlags(&evKV, cudaEventDisableTiming);
        cudaEventCreateWithFlags(&evQ,  cudaEventDisableTiming);
        cudaFuncSetAttribute(qkv_mma_kernel,
                             cudaFuncAttributeMaxDynamicSharedMemorySize, 2 * STG2);
        cudaFuncSetAttribute(ktv_mma_kernel,
                             cudaFuncAttributeMaxDynamicSharedMemorySize, 2 * TILE3);
        cudaFuncSetAttribute(out_mma_kernel,
                             cudaFuncAttributeMaxDynamicSharedMemorySize, QTILE + TILE3);
    }

    // s0: W cvt, then x cvt in 2 halves (each large enough for full HBM BW).
    cvt_w_kernel<<<384, 256>>>(Wq, Wk, Wv);
    cvt_x_kernel<<<8192, 256>>>(x, 0);
    cudaEventRecord(evA, 0);
    cvt_x_kernel<<<8192, 256>>>(x, 1);
    cudaEventRecord(evB, 0);

    // s2: kv projection in 2 row-halves, pipelined behind cvt halves.
    cudaStreamWaitEvent(s2, evA, 0);
    qkv_mma_kernel<<<dim3(64, 2), 256, 2 * STG2, s2>>>(bq, bk, bv, 1, 0);
    cudaStreamWaitEvent(s2, evB, 0);
    qkv_mma_kernel<<<dim3(64, 2), 256, 2 * STG2, s2>>>(bq, bk, bv, 1, 8192);
    cudaEventRecord(evKV, s2);

    // s2: q projection (all rows; x complete by stream order on s2).
    qkv_mma_kernel<<<dim3(128, 1), 256, 2 * STG2, s2>>>(bq, bk, bv, 0, 0);
    cudaEventRecord(evQ, s2);

    // s0: ktv + reduce overlap q projection.
    cudaStreamWaitEvent(0, evKV, 0);
    ktv_mma_kernel<<<dim3(TSPL, BATCH), 256, 2 * TILE3>>>();
    reduce_m_kernel<<<64, 256>>>();

    // Join and finish.
    cudaStreamWaitEvent(0, evQ, 0);
    out_mma_kernel<<<dim3(SEQ / 64, BATCH), 256, QTILE + TILE3>>>(out);
}

// round 14
// speedup vs baseline: 1.2262x; 1.2262x over previous
#include <cuda_runtime.h>
#include <cuda_fp16.h>
#include <cstdint>

#define D      128
#define DM     1024
#define BATCH  4
#define SEQ    4096
#define ROWS   (BATCH * SEQ)   // 16384
#define TSPL   16              // ktv split count
#define NCH2   16              // qkv K chunks of 64

// Scratch (allocation-free rule: __device__ globals)
__device__ __half g_xh[(size_t)ROWS * DM];
__device__ __half g_wh[3 * D * DM];
__device__ __half g_qh[ROWS * D];
__device__ __half g_kh[ROWS * D];
__device__ __half g_vh[ROWS * D];
__device__ float  g_mpart[BATCH * TSPL * D * D];
__device__ __half g_mh[BATCH * D * D];

// ===========================================================================
// helpers (sm_80-era PTX: ldmatrix / mma.sync / cp.async)
// ===========================================================================
__device__ __forceinline__ uint32_t s2u(const void* p) {
    uint32_t a;
    asm("{ .reg .u64 t; cvta.to.shared.u64 t, %1; cvt.u32.u64 %0, t; }"
        : "=r"(a) : "l"(p));
    return a;
}
__device__ __forceinline__ void ldsm4(uint32_t* r, uint32_t addr) {
    asm volatile("ldmatrix.sync.aligned.m8n8.x4.shared.b16 {%0,%1,%2,%3}, [%4];"
                 : "=r"(r[0]), "=r"(r[1]), "=r"(r[2]), "=r"(r[3]) : "r"(addr));
}
__device__ __forceinline__ void ldsm4t(uint32_t* r, uint32_t addr) {
    asm volatile("ldmatrix.sync.aligned.m8n8.x4.trans.shared.b16 {%0,%1,%2,%3}, [%4];"
                 : "=r"(r[0]), "=r"(r[1]), "=r"(r[2]), "=r"(r[3]) : "r"(addr));
}
__device__ __forceinline__ void mma_fp16(float* d, const uint32_t* a,
                                         uint32_t b0, uint32_t b1) {
    asm volatile(
        "mma.sync.aligned.m16n8k16.row.col.f32.f16.f16.f32 "
        "{%0,%1,%2,%3}, {%4,%5,%6,%7}, {%8,%9}, {%0,%1,%2,%3};"
        : "+f"(d[0]), "+f"(d[1]), "+f"(d[2]), "+f"(d[3])
        : "r"(a[0]), "r"(a[1]), "r"(a[2]), "r"(a[3]), "r"(b0), "r"(b1));
}
__device__ __forceinline__ void cpa16(uint32_t dst, const void* src) {
    asm volatile("cp.async.cg.shared.global [%0], [%1], 16;" :: "r"(dst), "l"(src));
}
__device__ __forceinline__ uint32_t pk2(float a, float b) {
    __half2 h = __floats2half2_rn(a, b);
    return *(uint32_t*)&h;
}

// ===========================================================================
// Kernel 0: convert x -> fp16 hi; W -> fp16 hi.  (R10 proven version)
// ===========================================================================
__global__ __launch_bounds__(256) void cvt_kernel(
    const float* __restrict__ x,
    const float* __restrict__ Wq, const float* __restrict__ Wk,
    const float* __restrict__ Wv)
{
    const size_t NX = (size_t)ROWS * DM;           // 16,777,216
    size_t i4 = ((size_t)blockIdx.x * 256 + threadIdx.x) * 4;

    if (i4 < NX) {
        float4 v = *(const float4*)&x[i4];
        *(uint32_t*)&g_xh[i4]     = pk2(v.x, v.y);
        *(uint32_t*)&g_xh[i4 + 2] = pk2(v.z, v.w);
    } else {
        size_t j = i4 - NX;
        if (j >= (size_t)3 * D * DM) return;
        size_t w = j >> 17;                         // which W
        const float* src = (w == 0) ? Wq : (w == 1) ? Wk : Wv;
        size_t off = j & 131071;
        float4 v = *(const float4*)&src[off];
        *(uint32_t*)&g_wh[j]     = pk2(v.x, v.y);
        *(uint32_t*)&g_wh[j + 2] = pk2(v.z, v.w);
    }
}

// ===========================================================================
// Kernel 1: KV projection, 1-term fp16 mma. head = 1 + blockIdx.y (k, v).
// CTA 128x128xK64 double buffered; warps 4M x 2N (warp 32x64). fp16-hi out.
// ===========================================================================
#define TS2   144                 // smem bytes per row (128 data + 16 pad)
#define TILE2 (128 * TS2)         // 18432
#define STG2  (2 * TILE2)         // 36864 per stage (Ah, Bh)

__global__ __launch_bounds__(256, 2) void kv_mma_kernel(
    const float* __restrict__ bk, const float* __restrict__ bv)
{
    extern __shared__ char smem[];
    const uint32_t sb = s2u(smem);

    const int tid  = threadIdx.x;
    const int lane = tid & 31;
    const int wid  = tid >> 5;
    const int wm   = wid & 3;        // 32-row M block
    const int wn   = wid >> 2;       // 64-col N block
    const int head = 1 + blockIdx.y;
    const int row0 = blockIdx.x * 128;

    const __half* Ahg = g_xh + (size_t)row0 * DM;
    const __half* Bhg = g_wh + ((size_t)head << 17);
    const float* bias = (head == 1) ? bk : bv;
    __half* oh = (head == 1) ? g_kh : g_vh;

    // cp.async mapping: 128 rows x 8 16B-units = 1024 slots, 4 per thread/tile.
    int cr[4], cu[4];
    #pragma unroll
    for (int i = 0; i < 4; i++) {
        int slot = tid + i * 256;
        cr[i] = slot >> 3;
        cu[i] = slot & 7;
    }

    #define QISSUE(c) do {                                                     \
        uint32_t _b = sb + ((c) & 1) * STG2;                                   \
        _Pragma("unroll")                                                      \
        for (int _i = 0; _i < 4; _i++) {                                       \
            uint32_t _so = (uint32_t)(cr[_i] * TS2 + cu[_i] * 16);             \
            size_t _go = (size_t)cr[_i] * DM + (c) * 64 + cu[_i] * 8;          \
            cpa16(_b + _so,         Ahg + _go);                                \
            cpa16(_b + TILE2 + _so, Bhg + _go);                                \
        }                                                                      \
    } while (0)

    float acc[2][8][4];
    #pragma unroll
    for (int i = 0; i < 2; i++)
        #pragma unroll
        for (int j = 0; j < 8; j++)
            #pragma unroll
            for (int q = 0; q < 4; q++) acc[i][j][q] = 0.0f;

    QISSUE(0);
    asm volatile("cp.async.commit_group;" ::: "memory");
    QISSUE(1);
    asm volatile("cp.async.commit_group;" ::: "memory");

    const uint32_t lrA = (uint32_t)(wm * 32 + (lane & 15));
    const uint32_t lcb = (uint32_t)((lane >> 4) << 4);

    for (int c = 0; c < NCH2; c++) {
        asm volatile("cp.async.wait_group 1;" ::: "memory");
        __syncthreads();

        uint32_t base = sb + (c & 1) * STG2;
        uint32_t aH = base, bH = base + TILE2;

        #pragma unroll
        for (int ks = 0; ks < 4; ks++) {
            uint32_t kb = (uint32_t)(ks * 32) + lcb;
            uint32_t ah[8];
            ldsm4(ah,     aH + lrA * TS2 + kb);
            ldsm4(ah + 4, aH + (lrA + 16) * TS2 + kb);
            #pragma unroll
            for (int nb = 0; nb < 4; nb++) {
                uint32_t rb = (uint32_t)(wn * 64 + nb * 16 + (lane & 15));
                uint32_t bh[4];
                ldsm4(bh, bH + rb * TS2 + kb);
                #pragma unroll
                for (int ma = 0; ma < 2; ma++) {
                    mma_fp16(acc[ma][nb*2+0], ah + ma*4, bh[0], bh[2]);
                    mma_fp16(acc[ma][nb*2+1], ah + ma*4, bh[1], bh[3]);
                }
            }
        }
        __syncthreads();
        if (c + 2 < NCH2) QISSUE(c + 2);
        asm volatile("cp.async.commit_group;" ::: "memory");
    }

    // Epilogue: add bias, store fp16 hi.
    const int g8  = lane >> 2;
    const int t4  = lane & 3;
    #pragma unroll
    for (int ma = 0; ma < 2; ma++) {
        int r = row0 + wm * 32 + ma * 16 + g8;
        #pragma unroll
        for (int na = 0; na < 8; na++) {
            int col = wn * 64 + na * 8 + t4 * 2;
            float bx = __ldg(&bias[col]), by = __ldg(&bias[col + 1]);
            *(uint32_t*)&oh[(size_t)r * D + col] =
                pk2(acc[ma][na][0] + bx, acc[ma][na][1] + by);
            *(uint32_t*)&oh[(size_t)(r + 8) * D + col] =
                pk2(acc[ma][na][2] + bx, acc[ma][na][3] + by);
        }
    }
}

// ===========================================================================
// Kernel 1q: Q projection with 64-row M tiles -> 256 CTAs (~2/SM).
// CTA 64x128xK64 double buffered; warps 2M x 4N (warp 32x32). fp16-hi out.
// smem/stage: A 64*144=9216 + B 18432 = 27648; x2 = 55296.
// ===========================================================================
#define A64T  (64 * TS2)          // 9216
#define STGQ  (A64T + TILE2)      // 27648

__global__ __launch_bounds__(256, 2) void q_mma_kernel(
    const float* __restrict__ bq)
{
    extern __shared__ char smem[];
    const uint32_t sb = s2u(smem);

    const int tid  = threadIdx.x;
    const int lane = tid & 31;
    const int wid  = tid >> 5;
    const int wm   = wid & 1;        // 32-row M block (2)
    const int wn   = wid >> 1;       // 32-col N block (4)
    const int row0 = blockIdx.x * 64;

    const __half* Ahg = g_xh + (size_t)row0 * DM;
    const __half* Bhg = g_wh;        // head 0 = q

    // cp.async: A 64 rows x 8 units = 512 slots (2/thread);
    //           B 128 rows x 8 units = 1024 slots (4/thread).
    const int ar = tid >> 3, au = tid & 7;          // + i*32 rows (2 iters)
    int cr[4], cu[4];
    #pragma unroll
    for (int i = 0; i < 4; i++) {
        int slot = tid + i * 256;
        cr[i] = slot >> 3;
        cu[i] = slot & 7;
    }

    #define QISSUE64(c) do {                                                   \
        uint32_t _b = sb + ((c) & 1) * STGQ;                                   \
        _Pragma("unroll")                                                      \
        for (int _i = 0; _i < 2; _i++) {                                       \
            int _r = ar + _i * 32;                                             \
            cpa16(_b + (uint32_t)(_r * TS2 + au * 16),                         \
                  Ahg + (size_t)_r * DM + (c) * 64 + au * 8);                  \
        }                                                                      \
        _Pragma("unroll")                                                      \
        for (int _i = 0; _i < 4; _i++) {                                       \
            cpa16(_b + A64T + (uint32_t)(cr[_i] * TS2 + cu[_i] * 16),          \
                  Bhg + (size_t)cr[_i] * DM + (c) * 64 + cu[_i] * 8);          \
        }                                                                      \
    } while (0)

    float acc[2][4][4];
    #pragma unroll
    for (int i = 0; i < 2; i++)
        #pragma unroll
        for (int j = 0; j < 4; j++)
            #pragma unroll
            for (int q = 0; q < 4; q++) acc[i][j][q] = 0.0f;

    QISSUE64(0);
    asm volatile("cp.async.commit_group;" ::: "memory");
    QISSUE64(1);
    asm volatile("cp.async.commit_group;" ::: "memory");

    const uint32_t lrA = (uint32_t)(wm * 32 + (lane & 15));
    const uint32_t lcb = (uint32_t)((lane >> 4) << 4);

    for (int c = 0; c < NCH2; c++) {
        asm volatile("cp.async.wait_group 1;" ::: "memory");
        __syncthreads();

        uint32_t base = sb + (c & 1) * STGQ;
        uint32_t aH = base, bH = base + A64T;

        #pragma unroll
        for (int ks = 0; ks < 4; ks++) {
            uint32_t kb = (uint32_t)(ks * 32) + lcb;
            uint32_t ah[8];
            ldsm4(ah,     aH + lrA * TS2 + kb);
            ldsm4(ah + 4, aH + (lrA + 16) * TS2 + kb);
            #pragma unroll
            for (int nb = 0; nb < 2; nb++) {
                uint32_t rb = (uint32_t)(wn * 32 + nb * 16 + (lane & 15));
                uint32_t bh[4];
                ldsm4(bh, bH + rb * TS2 + kb);
                #pragma unroll
                for (int ma = 0; ma < 2; ma++) {
                    mma_fp16(acc[ma][nb*2+0], ah + ma*4, bh[0], bh[2]);
                    mma_fp16(acc[ma][nb*2+1], ah + ma*4, bh[1], bh[3]);
                }
            }
        }
        __syncthreads();
        if (c + 2 < NCH2) QISSUE64(c + 2);
        asm volatile("cp.async.commit_group;" ::: "memory");
    }

    // Epilogue: add bias, store fp16 hi.
    const int g8  = lane >> 2;
    const int t4  = lane & 3;
    #pragma unroll
    for (int ma = 0; ma < 2; ma++) {
        int r = row0 + wm * 32 + ma * 16 + g8;
        #pragma unroll
        for (int na = 0; na < 4; na++) {
            int col = wn * 32 + na * 8 + t4 * 2;
            float bx = __ldg(&bq[col]), by = __ldg(&bq[col + 1]);
            *(uint32_t*)&g_qh[(size_t)r * D + col] =
                pk2(acc[ma][na][0] + bx, acc[ma][na][1] + by);
            *(uint32_t*)&g_qh[(size_t)(r + 8) * D + col] =
                pk2(acc[ma][na][2] + bx, acc[ma][na][3] + by);
        }
    }
}

// ===========================================================================
// Kernel 2a: ktv partials on tensor cores, 1-term fp16.
// M_part[d,e] = sum_{t in split} kh[t,d] * vh[t,e]; 256 t-rows per CTA.
// ===========================================================================
#define TS3   272                 // 256 data + 16 pad
#define TILE3 (128 * TS3)         // 34816

__global__ __launch_bounds__(256) void ktv_mma_kernel()
{
    extern __shared__ char smem[];
    const uint32_t sb = s2u(smem);
    const uint32_t sKh = sb, sVh = sb + TILE3;

    const int tid  = threadIdx.x;
    const int lane = tid & 31;
    const int wid  = tid >> 5;
    const int wm   = wid & 3;        // d block (32)
    const int wn   = wid >> 2;       // e block (64)
    const int b    = blockIdx.y;
    const int t0   = blockIdx.x * 256;

    float acc[2][8][4];
    #pragma unroll
    for (int i = 0; i < 2; i++)
        #pragma unroll
        for (int j = 0; j < 8; j++)
            #pragma unroll
            for (int q = 0; q < 4; q++) acc[i][j][q] = 0.0f;

    const uint32_t trow = (uint32_t)(((lane >> 4) & 1) * 8 + (lane & 7));
    const uint32_t tcb  = (uint32_t)(((lane >> 3) & 1) * 16);

    for (int cc = 0; cc < 2; cc++) {
        const __half* khg = g_kh + ((size_t)b * SEQ + t0 + cc * 128) * D;
        const __half* vhg = g_vh + ((size_t)b * SEQ + t0 + cc * 128) * D;

        #pragma unroll
        for (int i = 0; i < 8; i++) {
            int slot = tid + i * 256;          // 2048 slots: 128 rows x 16 units
            int r = slot >> 4, u = slot & 15;
            uint32_t so = (uint32_t)(r * TS3 + u * 16);
            size_t go = (size_t)r * D + u * 8;
            cpa16(sKh + so, khg + go);
            cpa16(sVh + so, vhg + go);
        }
        asm volatile("cp.async.commit_group;" ::: "memory");
        asm volatile("cp.async.wait_group 0;" ::: "memory");
        __syncthreads();

        #pragma unroll
        for (int ks = 0; ks < 8; ks++) {
            uint32_t aoff = ((uint32_t)(ks * 16) + trow) * TS3 + tcb;
            uint32_t ah[8];
            ldsm4t(ah,     sKh + aoff + wm * 64);
            ldsm4t(ah + 4, sKh + aoff + wm * 64 + 32);
            #pragma unroll
            for (int nb = 0; nb < 4; nb++) {
                uint32_t eb = (uint32_t)(wn * 128 + nb * 32);
                uint32_t bh[4];
                ldsm4t(bh, sVh + aoff + eb);
                #pragma unroll
                for (int ma = 0; ma < 2; ma++) {
                    mma_fp16(acc[ma][nb*2+0], ah + ma*4, bh[0], bh[2]);
                    mma_fp16(acc[ma][nb*2+1], ah + ma*4, bh[1], bh[3]);
                }
            }
        }
        __syncthreads();
    }

    float* outp = g_mpart + ((size_t)(b * TSPL + blockIdx.x) << 14);
    const int g8 = lane >> 2;
    const int t4 = lane & 3;
    #pragma unroll
    for (int ma = 0; ma < 2; ma++) {
        int r = wm * 32 + ma * 16 + g8;
        #pragma unroll
        for (int na = 0; na < 8; na++) {
            int col = wn * 64 + na * 8 + t4 * 2;
            *(float2*)&outp[(size_t)r * D + col] =
                make_float2(acc[ma][na][0], acc[ma][na][1]);
            *(float2*)&outp[(size_t)(r + 8) * D + col] =
                make_float2(acc[ma][na][2], acc[ma][na][3]);
        }
    }
}

// ===========================================================================
// Kernel 2b: reduce partials -> Mh fp16 (vectorized float4).
// ===========================================================================
__global__ __launch_bounds__(256) void reduce_m_kernel()
{
    int s  = blockIdx.x * 256 + threadIdx.x;     // 0..16383 (float4 slots)
    int b  = s >> 12;                            // 4096 slots per batch
    int sl = s & 4095;
    const float4* mp4 = (const float4*)g_mpart + ((size_t)b * TSPL << 12);
    float4 sum = make_float4(0.f, 0.f, 0.f, 0.f);
    #pragma unroll
    for (int p = 0; p < TSPL; p++) {
        float4 v = mp4[((size_t)p << 12) + sl];
        sum.x += v.x; sum.y += v.y; sum.z += v.z; sum.w += v.w;
    }
    int idx = s * 4;
    *(uint32_t*)&g_mh[idx]     = pk2(sum.x, sum.y);
    *(uint32_t*)&g_mh[idx + 2] = pk2(sum.z, sum.w);
}

// ===========================================================================
// Kernel 3: out = scale * q @ Mh, 1-term fp16, 64-row Q tiles (256 CTAs).
// A = qh [s][d] (non-trans); B = Mh [d][e] via ldmatrix.trans.
// Warps: 2M x 4N (warp 32x32).
// ===========================================================================
#define QTILE (64 * TS3)          // 17408

__global__ __launch_bounds__(256) void out_mma_kernel(float* __restrict__ out)
{
    extern __shared__ char smem[];
    const uint32_t sb = s2u(smem);
    const uint32_t sQh = sb, sMh = sb + QTILE;

    const int tid  = threadIdx.x;
    const int lane = tid & 31;
    const int wid  = tid >> 5;
    const int wm   = wid & 1;        // s block (32)
    const int wn   = wid >> 1;       // e block (32)
    const int b    = blockIdx.y;
    const int s0   = blockIdx.x * 64;

    const __half* qhg = g_qh + ((size_t)b * SEQ + s0) * D;
    const __half* mhg = g_mh + ((size_t)b << 14);

    #pragma unroll
    for (int i = 0; i < 4; i++) {
        int slot = tid + i * 256;
        int r = slot >> 4, u = slot & 15;
        cpa16(sQh + (uint32_t)(r * TS3 + u * 16), qhg + (size_t)r * D + u * 8);
    }
    #pragma unroll
    for (int i = 0; i < 8; i++) {
        int slot = tid + i * 256;
        int r = slot >> 4, u = slot & 15;
        cpa16(sMh + (uint32_t)(r * TS3 + u * 16), mhg + (size_t)r * D + u * 8);
    }
    asm volatile("cp.async.commit_group;" ::: "memory");
    asm volatile("cp.async.wait_group 0;" ::: "memory");
    __syncthreads();

    float acc[2][4][4];
    #pragma unroll
    for (int i = 0; i < 2; i++)
        #pragma unroll
        for (int j = 0; j < 4; j++)
            #pragma unroll
            for (int q = 0; q < 4; q++) acc[i][j][q] = 0.0f;

    const uint32_t lrA  = (uint32_t)(wm * 32 + (lane & 15));
    const uint32_t lcb  = (uint32_t)((lane >> 4) << 4);
    const uint32_t trow = (uint32_t)(((lane >> 4) & 1) * 8 + (lane & 7));
    const uint32_t tcb  = (uint32_t)(((lane >> 3) & 1) * 16);

    #pragma unroll
    for (int ks = 0; ks < 8; ks++) {
        uint32_t kb = (uint32_t)(ks * 32) + lcb;
        uint32_t ah[8];
        ldsm4(ah,     sQh + lrA * TS3 + kb);
        ldsm4(ah + 4, sQh + (lrA + 16) * TS3 + kb);
        uint32_t boff = ((uint32_t)(ks * 16) + trow) * TS3 + tcb;
        #pragma unroll
        for (int nb = 0; nb < 2; nb++) {
            uint32_t eb = (uint32_t)(wn * 64 + nb * 32);
            uint32_t bh[4];
            ldsm4t(bh, sMh + boff + eb);
            #pragma unroll
            for (int ma = 0; ma < 2; ma++) {
                mma_fp16(acc[ma][nb*2+0], ah + ma*4, bh[0], bh[2]);
                mma_fp16(acc[ma][nb*2+1], ah + ma*4, bh[1], bh[3]);
            }
        }
    }

    const float scale = 0.08838834764831845f;    // 128^-0.5
    const int g8 = lane >> 2;
    const int t4 = lane & 3;
    #pragma unroll
    for (int ma = 0; ma < 2; ma++) {
        int r = s0 + wm * 32 + ma * 16 + g8;
        #pragma unroll
        for (int na = 0; na < 4; na++) {
            int col = wn * 32 + na * 8 + t4 * 2;
            *(float2*)&out[((size_t)b * SEQ + r) * D + col] =
                make_float2(acc[ma][na][0] * scale, acc[ma][na][1] * scale);
            *(float2*)&out[((size_t)b * SEQ + r + 8) * D + col] =
                make_float2(acc[ma][na][2] * scale, acc[ma][na][3] * scale);
        }
    }
}

// ---------------------------------------------------------------------------
extern "C" void kernel_launch(void* const* d_in, const int* in_sizes, int n_in,
                              void* d_out, int out_size)
{
    const float* x  = (const float*)d_in[0];
    const float* Wq = (const float*)d_in[1];
    const float* bq = (const float*)d_in[2];
    const float* Wk = (const float*)d_in[3];
    const float* bk = (const float*)d_in[4];
    const float* Wv = (const float*)d_in[5];
    const float* bv = (const float*)d_in[6];
    float* out = (float*)d_out;

    static cudaStream_t s2 = nullptr;
    static cudaEvent_t evKV = nullptr, evQ = nullptr;
    if (s2 == nullptr) {
        cudaStreamCreateWithFlags(&s2, cudaStreamNonBlocking);
        cudaEventCreateWithFlags(&evKV, cudaEventDisableTiming);
        cudaEventCreateWithFlags(&evQ,  cudaEventDisableTiming);
        cudaFuncSetAttribute(kv_mma_kernel,
                             cudaFuncAttributeMaxDynamicSharedMemorySize, 2 * STG2);
        cudaFuncSetAttribute(q_mma_kernel,
                             cudaFuncAttributeMaxDynamicSharedMemorySize, 2 * STGQ);
        cudaFuncSetAttribute(ktv_mma_kernel,
                             cudaFuncAttributeMaxDynamicSharedMemorySize, 2 * TILE3);
        cudaFuncSetAttribute(out_mma_kernel,
                             cudaFuncAttributeMaxDynamicSharedMemorySize, QTILE + TILE3);
    }

    // Main stream: cvt -> kv projection -> ktv -> reduce -> (join q) -> out.
    cvt_kernel<<<16768, 256>>>(x, Wq, Wk, Wv);
    kv_mma_kernel<<<dim3(ROWS / 128, 2), 256, 2 * STG2>>>(bk, bv);
    cudaEventRecord(evKV, 0);

    // Fork: q projection (64-row tiles, 256 CTAs) overlaps ktv+reduce.
    cudaStreamWaitEvent(s2, evKV, 0);
    q_mma_kernel<<<dim3(ROWS / 64), 256, 2 * STGQ, s2>>>(bq);
    cudaEventRecord(evQ, s2);

    ktv_mma_kernel<<<dim3(TSPL, BATCH), 256, 2 * TILE3>>>();
    reduce_m_kernel<<<64, 256>>>();

    // Join and finish.
    cudaStreamWaitEvent(0, evQ, 0);
    out_mma_kernel<<<dim3(SEQ / 64, BATCH), 256, QTILE + TILE3>>>(out);
}

// round 15
// speedup vs baseline: 1.3069x; 1.0659x over previous
#include <cuda_runtime.h>
#include <cuda_fp16.h>
#include <cstdint>

#define D      128
#define DM     1024
#define BATCH  4
#define SEQ    4096
#define ROWS   (BATCH * SEQ)   // 16384
#define TSPL   16              // ktv split count
#define NCH2   16              // qkv K chunks of 64

// Scratch (allocation-free rule: __device__ globals)
__device__ __half g_xh[(size_t)ROWS * DM];
__device__ __half g_wh[3 * D * DM];
__device__ __half g_qh[ROWS * D];
__device__ __half g_kh[ROWS * D];
__device__ __half g_vh[ROWS * D];
__device__ float  g_mpart[BATCH * TSPL * D * D];
__device__ __half g_mh[BATCH * D * D];

// ===========================================================================
// helpers (sm_80-era PTX: ldmatrix / mma.sync / cp.async)
// ===========================================================================
__device__ __forceinline__ uint32_t s2u(const void* p) {
    uint32_t a;
    asm("{ .reg .u64 t; cvta.to.shared.u64 t, %1; cvt.u32.u64 %0, t; }"
        : "=r"(a) : "l"(p));
    return a;
}
__device__ __forceinline__ void ldsm4(uint32_t* r, uint32_t addr) {
    asm volatile("ldmatrix.sync.aligned.m8n8.x4.shared.b16 {%0,%1,%2,%3}, [%4];"
                 : "=r"(r[0]), "=r"(r[1]), "=r"(r[2]), "=r"(r[3]) : "r"(addr));
}
__device__ __forceinline__ void ldsm4t(uint32_t* r, uint32_t addr) {
    asm volatile("ldmatrix.sync.aligned.m8n8.x4.trans.shared.b16 {%0,%1,%2,%3}, [%4];"
                 : "=r"(r[0]), "=r"(r[1]), "=r"(r[2]), "=r"(r[3]) : "r"(addr));
}
__device__ __forceinline__ void mma_fp16(float* d, const uint32_t* a,
                                         uint32_t b0, uint32_t b1) {
    asm volatile(
        "mma.sync.aligned.m16n8k16.row.col.f32.f16.f16.f32 "
        "{%0,%1,%2,%3}, {%4,%5,%6,%7}, {%8,%9}, {%0,%1,%2,%3};"
        : "+f"(d[0]), "+f"(d[1]), "+f"(d[2]), "+f"(d[3])
        : "r"(a[0]), "r"(a[1]), "r"(a[2]), "r"(a[3]), "r"(b0), "r"(b1));
}
__device__ __forceinline__ void cpa16(uint32_t dst, const void* src) {
    asm volatile("cp.async.cg.shared.global [%0], [%1], 16;" :: "r"(dst), "l"(src));
}
__device__ __forceinline__ uint32_t pk2(float a, float b) {
    __half2 h = __floats2half2_rn(a, b);
    return *(uint32_t*)&h;
}

// ===========================================================================
// Kernel 0: convert x -> fp16 hi; W -> fp16 hi.  (R10 proven version)
// ===========================================================================
__global__ __launch_bounds__(256) void cvt_kernel(
    const float* __restrict__ x,
    const float* __restrict__ Wq, const float* __restrict__ Wk,
    const float* __restrict__ Wv)
{
    const size_t NX = (size_t)ROWS * DM;           // 16,777,216
    size_t i4 = ((size_t)blockIdx.x * 256 + threadIdx.x) * 4;

    if (i4 < NX) {
        float4 v = *(const float4*)&x[i4];
        *(uint32_t*)&g_xh[i4]     = pk2(v.x, v.y);
        *(uint32_t*)&g_xh[i4 + 2] = pk2(v.z, v.w);
    } else {
        size_t j = i4 - NX;
        if (j >= (size_t)3 * D * DM) return;
        size_t w = j >> 17;                         // which W
        const float* src = (w == 0) ? Wq : (w == 1) ? Wk : Wv;
        size_t off = j & 131071;
        float4 v = *(const float4*)&src[off];
        *(uint32_t*)&g_wh[j]     = pk2(v.x, v.y);
        *(uint32_t*)&g_wh[j + 2] = pk2(v.z, v.w);
    }
}

// ===========================================================================
// Kernel 1: KV projection (R10 proven). head = 1 + blockIdx.y (k, v).
// CTA 128x128xK64 double buffered; 256 thr, warps 4M x 2N. fp16-hi out.
// ===========================================================================
#define TS2   144                 // smem bytes per row (128 data + 16 pad)
#define TILE2 (128 * TS2)         // 18432
#define STG2  (2 * TILE2)         // 36864 per stage (Ah, Bh)

__global__ __launch_bounds__(256, 2) void kv_mma_kernel(
    const float* __restrict__ bk, const float* __restrict__ bv)
{
    extern __shared__ char smem[];
    const uint32_t sb = s2u(smem);

    const int tid  = threadIdx.x;
    const int lane = tid & 31;
    const int wid  = tid >> 5;
    const int wm   = wid & 3;        // 32-row M block
    const int wn   = wid >> 2;       // 64-col N block
    const int head = 1 + blockIdx.y;
    const int row0 = blockIdx.x * 128;

    const __half* Ahg = g_xh + (size_t)row0 * DM;
    const __half* Bhg = g_wh + ((size_t)head << 17);
    const float* bias = (head == 1) ? bk : bv;
    __half* oh = (head == 1) ? g_kh : g_vh;

    int cr[4], cu[4];
    #pragma unroll
    for (int i = 0; i < 4; i++) {
        int slot = tid + i * 256;
        cr[i] = slot >> 3;
        cu[i] = slot & 7;
    }

    #define KVISSUE(c) do {                                                    \
        uint32_t _b = sb + ((c) & 1) * STG2;                                   \
        _Pragma("unroll")                                                      \
        for (int _i = 0; _i < 4; _i++) {                                       \
            uint32_t _so = (uint32_t)(cr[_i] * TS2 + cu[_i] * 16);             \
            size_t _go = (size_t)cr[_i] * DM + (c) * 64 + cu[_i] * 8;          \
            cpa16(_b + _so,         Ahg + _go);                                \
            cpa16(_b + TILE2 + _so, Bhg + _go);                                \
        }                                                                      \
    } while (0)

    float acc[2][8][4];
    #pragma unroll
    for (int i = 0; i < 2; i++)
        #pragma unroll
        for (int j = 0; j < 8; j++)
            #pragma unroll
            for (int q = 0; q < 4; q++) acc[i][j][q] = 0.0f;

    KVISSUE(0);
    asm volatile("cp.async.commit_group;" ::: "memory");
    KVISSUE(1);
    asm volatile("cp.async.commit_group;" ::: "memory");

    const uint32_t lrA = (uint32_t)(wm * 32 + (lane & 15));
    const uint32_t lcb = (uint32_t)((lane >> 4) << 4);

    for (int c = 0; c < NCH2; c++) {
        asm volatile("cp.async.wait_group 1;" ::: "memory");
        __syncthreads();

        uint32_t base = sb + (c & 1) * STG2;
        uint32_t aH = base, bH = base + TILE2;

        #pragma unroll
        for (int ks = 0; ks < 4; ks++) {
            uint32_t kb = (uint32_t)(ks * 32) + lcb;
            uint32_t ah[8];
            ldsm4(ah,     aH + lrA * TS2 + kb);
            ldsm4(ah + 4, aH + (lrA + 16) * TS2 + kb);
            #pragma unroll
            for (int nb = 0; nb < 4; nb++) {
                uint32_t rb = (uint32_t)(wn * 64 + nb * 16 + (lane & 15));
                uint32_t bh[4];
                ldsm4(bh, bH + rb * TS2 + kb);
                #pragma unroll
                for (int ma = 0; ma < 2; ma++) {
                    mma_fp16(acc[ma][nb*2+0], ah + ma*4, bh[0], bh[2]);
                    mma_fp16(acc[ma][nb*2+1], ah + ma*4, bh[1], bh[3]);
                }
            }
        }
        __syncthreads();
        if (c + 2 < NCH2) KVISSUE(c + 2);
        asm volatile("cp.async.commit_group;" ::: "memory");
    }

    const int g8  = lane >> 2;
    const int t4  = lane & 3;
    #pragma unroll
    for (int ma = 0; ma < 2; ma++) {
        int r = row0 + wm * 32 + ma * 16 + g8;
        #pragma unroll
        for (int na = 0; na < 8; na++) {
            int col = wn * 64 + na * 8 + t4 * 2;
            float bx = __ldg(&bias[col]), by = __ldg(&bias[col + 1]);
            *(uint32_t*)&oh[(size_t)r * D + col] =
                pk2(acc[ma][na][0] + bx, acc[ma][na][1] + by);
            *(uint32_t*)&oh[(size_t)(r + 8) * D + col] =
                pk2(acc[ma][na][2] + bx, acc[ma][na][3] + by);
        }
    }
}

// ===========================================================================
// Kernel 1q: Q projection, 512 threads (16 warps) for latency hiding.
// CTA 128x128xK64 double buffered; warps 4M x 4N (warp 32x32). fp16-hi out.
// Same tiles/arithmetic as kv; only warp count/partition differs.
// ===========================================================================
__global__ __launch_bounds__(512, 1) void q_mma_kernel(
    const float* __restrict__ bq)
{
    extern __shared__ char smem[];
    const uint32_t sb = s2u(smem);

    const int tid  = threadIdx.x;
    const int lane = tid & 31;
    const int wid  = tid >> 5;       // 0..15
    const int wm   = wid & 3;        // 32-row M block (4)
    const int wn   = wid >> 2;       // 32-col N block (4)
    const int row0 = blockIdx.x * 128;

    const __half* Ahg = g_xh + (size_t)row0 * DM;
    const __half* Bhg = g_wh;        // head 0 = q

    // cp.async: each tile 128 rows x 8 16B-units = 1024 slots; 512 thr -> 2 each.
    int cr[2], cu[2];
    #pragma unroll
    for (int i = 0; i < 2; i++) {
        int slot = tid + i * 512;
        cr[i] = slot >> 3;
        cu[i] = slot & 7;
    }

    #define QISSUE512(c) do {                                                  \
        uint32_t _b = sb + ((c) & 1) * STG2;                                   \
        _Pragma("unroll")                                                      \
        for (int _i = 0; _i < 2; _i++) {                                       \
            uint32_t _so = (uint32_t)(cr[_i] * TS2 + cu[_i] * 16);             \
            size_t _go = (size_t)cr[_i] * DM + (c) * 64 + cu[_i] * 8;          \
            cpa16(_b + _so,         Ahg + _go);                                \
            cpa16(_b + TILE2 + _so, Bhg + _go);                                \
        }                                                                      \
    } while (0)

    float acc[2][4][4];
    #pragma unroll
    for (int i = 0; i < 2; i++)
        #pragma unroll
        for (int j = 0; j < 4; j++)
            #pragma unroll
            for (int q = 0; q < 4; q++) acc[i][j][q] = 0.0f;

    QISSUE512(0);
    asm volatile("cp.async.commit_group;" ::: "memory");
    QISSUE512(1);
    asm volatile("cp.async.commit_group;" ::: "memory");

    const uint32_t lrA = (uint32_t)(wm * 32 + (lane & 15));
    const uint32_t lcb = (uint32_t)((lane >> 4) << 4);

    for (int c = 0; c < NCH2; c++) {
        asm volatile("cp.async.wait_group 1;" ::: "memory");
        __syncthreads();

        uint32_t base = sb + (c & 1) * STG2;
        uint32_t aH = base, bH = base + TILE2;

        #pragma unroll
        for (int ks = 0; ks < 4; ks++) {
            uint32_t kb = (uint32_t)(ks * 32) + lcb;
            uint32_t ah[8];
            ldsm4(ah,     aH + lrA * TS2 + kb);
            ldsm4(ah + 4, aH + (lrA + 16) * TS2 + kb);
            #pragma unroll
            for (int nb = 0; nb < 2; nb++) {
                uint32_t rb = (uint32_t)(wn * 32 + nb * 16 + (lane & 15));
                uint32_t bh[4];
                ldsm4(bh, bH + rb * TS2 + kb);
                #pragma unroll
                for (int ma = 0; ma < 2; ma++) {
                    mma_fp16(acc[ma][nb*2+0], ah + ma*4, bh[0], bh[2]);
                    mma_fp16(acc[ma][nb*2+1], ah + ma*4, bh[1], bh[3]);
                }
            }
        }
        __syncthreads();
        if (c + 2 < NCH2) QISSUE512(c + 2);
        asm volatile("cp.async.commit_group;" ::: "memory");
    }

    // Epilogue: add bias, store fp16 hi.
    const int g8  = lane >> 2;
    const int t4  = lane & 3;
    #pragma unroll
    for (int ma = 0; ma < 2; ma++) {
        int r = row0 + wm * 32 + ma * 16 + g8;
        #pragma unroll
        for (int na = 0; na < 4; na++) {
            int col = wn * 32 + na * 8 + t4 * 2;
            float bx = __ldg(&bq[col]), by = __ldg(&bq[col + 1]);
            *(uint32_t*)&g_qh[(size_t)r * D + col] =
                pk2(acc[ma][na][0] + bx, acc[ma][na][1] + by);
            *(uint32_t*)&g_qh[(size_t)(r + 8) * D + col] =
                pk2(acc[ma][na][2] + bx, acc[ma][na][3] + by);
        }
    }
}

// ===========================================================================
// Kernel 2a: ktv partials on tensor cores, 1-term fp16.
// M_part[d,e] = sum_{t in split} kh[t,d] * vh[t,e]; 256 t-rows per CTA.
// ===========================================================================
#define TS3   272                 // 256 data + 16 pad
#define TILE3 (128 * TS3)         // 34816

__global__ __launch_bounds__(256) void ktv_mma_kernel()
{
    extern __shared__ char smem[];
    const uint32_t sb = s2u(smem);
    const uint32_t sKh = sb, sVh = sb + TILE3;

    const int tid  = threadIdx.x;
    const int lane = tid & 31;
    const int wid  = tid >> 5;
    const int wm   = wid & 3;        // d block (32)
    const int wn   = wid >> 2;       // e block (64)
    const int b    = blockIdx.y;
    const int t0   = blockIdx.x * 256;

    float acc[2][8][4];
    #pragma unroll
    for (int i = 0; i < 2; i++)
        #pragma unroll
        for (int j = 0; j < 8; j++)
            #pragma unroll
            for (int q = 0; q < 4; q++) acc[i][j][q] = 0.0f;

    const uint32_t trow = (uint32_t)(((lane >> 4) & 1) * 8 + (lane & 7));
    const uint32_t tcb  = (uint32_t)(((lane >> 3) & 1) * 16);

    for (int cc = 0; cc < 2; cc++) {
        const __half* khg = g_kh + ((size_t)b * SEQ + t0 + cc * 128) * D;
        const __half* vhg = g_vh + ((size_t)b * SEQ + t0 + cc * 128) * D;

        #pragma unroll
        for (int i = 0; i < 8; i++) {
            int slot = tid + i * 256;          // 2048 slots: 128 rows x 16 units
            int r = slot >> 4, u = slot & 15;
            uint32_t so = (uint32_t)(r * TS3 + u * 16);
            size_t go = (size_t)r * D + u * 8;
            cpa16(sKh + so, khg + go);
            cpa16(sVh + so, vhg + go);
        }
        asm volatile("cp.async.commit_group;" ::: "memory");
        asm volatile("cp.async.wait_group 0;" ::: "memory");
        __syncthreads();

        #pragma unroll
        for (int ks = 0; ks < 8; ks++) {
            uint32_t aoff = ((uint32_t)(ks * 16) + trow) * TS3 + tcb;
            uint32_t ah[8];
            ldsm4t(ah,     sKh + aoff + wm * 64);
            ldsm4t(ah + 4, sKh + aoff + wm * 64 + 32);
            #pragma unroll
            for (int nb = 0; nb < 4; nb++) {
                uint32_t eb = (uint32_t)(wn * 128 + nb * 32);
                uint32_t bh[4];
                ldsm4t(bh, sVh + aoff + eb);
                #pragma unroll
                for (int ma = 0; ma < 2; ma++) {
                    mma_fp16(acc[ma][nb*2+0], ah + ma*4, bh[0], bh[2]);
                    mma_fp16(acc[ma][nb*2+1], ah + ma*4, bh[1], bh[3]);
                }
            }
        }
        __syncthreads();
    }

    float* outp = g_mpart + ((size_t)(b * TSPL + blockIdx.x) << 14);
    const int g8 = lane >> 2;
    const int t4 = lane & 3;
    #pragma unroll
    for (int ma = 0; ma < 2; ma++) {
        int r = wm * 32 + ma * 16 + g8;
        #pragma unroll
        for (int na = 0; na < 8; na++) {
            int col = wn * 64 + na * 8 + t4 * 2;
            *(float2*)&outp[(size_t)r * D + col] =
                make_float2(acc[ma][na][0], acc[ma][na][1]);
            *(float2*)&outp[(size_t)(r + 8) * D + col] =
                make_float2(acc[ma][na][2], acc[ma][na][3]);
        }
    }
}

// ===========================================================================
// Kernel 2b: reduce partials -> Mh fp16 (vectorized float4).
// ===========================================================================
__global__ __launch_bounds__(256) void reduce_m_kernel()
{
    int s  = blockIdx.x * 256 + threadIdx.x;     // 0..16383 (float4 slots)
    int b  = s >> 12;                            // 4096 slots per batch
    int sl = s & 4095;
    const float4* mp4 = (const float4*)g_mpart + ((size_t)b * TSPL << 12);
    float4 sum = make_float4(0.f, 0.f, 0.f, 0.f);
    #pragma unroll
    for (int p = 0; p < TSPL; p++) {
        float4 v = mp4[((size_t)p << 12) + sl];
        sum.x += v.x; sum.y += v.y; sum.z += v.z; sum.w += v.w;
    }
    int idx = s * 4;
    *(uint32_t*)&g_mh[idx]     = pk2(sum.x, sum.y);
    *(uint32_t*)&g_mh[idx + 2] = pk2(sum.z, sum.w);
}

// ===========================================================================
// Kernel 3: out = scale * q @ Mh, 1-term fp16, 64-row Q tiles (256 CTAs).
// A = qh [s][d] (non-trans); B = Mh [d][e] via ldmatrix.trans.
// Warps: 2M x 4N (warp 32x32).
// ===========================================================================
#define QTILE (64 * TS3)          // 17408

__global__ __launch_bounds__(256) void out_mma_kernel(float* __restrict__ out)
{
    extern __shared__ char smem[];
    const uint32_t sb = s2u(smem);
    const uint32_t sQh = sb, sMh = sb + QTILE;

    const int tid  = threadIdx.x;
    const int lane = tid & 31;
    const int wid  = tid >> 5;
    const int wm   = wid & 1;        // s block (32)
    const int wn   = wid >> 1;       // e block (32)
    const int b    = blockIdx.y;
    const int s0   = blockIdx.x * 64;

    const __half* qhg = g_qh + ((size_t)b * SEQ + s0) * D;
    const __half* mhg = g_mh + ((size_t)b << 14);

    #pragma unroll
    for (int i = 0; i < 4; i++) {
        int slot = tid + i * 256;
        int r = slot >> 4, u = slot & 15;
        cpa16(sQh + (uint32_t)(r * TS3 + u * 16), qhg + (size_t)r * D + u * 8);
    }
    #pragma unroll
    for (int i = 0; i < 8; i++) {
        int slot = tid + i * 256;
        int r = slot >> 4, u = slot & 15;
        cpa16(sMh + (uint32_t)(r * TS3 + u * 16), mhg + (size_t)r * D + u * 8);
    }
    asm volatile("cp.async.commit_group;" ::: "memory");
    asm volatile("cp.async.wait_group 0;" ::: "memory");
    __syncthreads();

    float acc[2][4][4];
    #pragma unroll
    for (int i = 0; i < 2; i++)
        #pragma unroll
        for (int j = 0; j < 4; j++)
            #pragma unroll
            for (int q = 0; q < 4; q++) acc[i][j][q] = 0.0f;

    const uint32_t lrA  = (uint32_t)(wm * 32 + (lane & 15));
    const uint32_t lcb  = (uint32_t)((lane >> 4) << 4);
    const uint32_t trow = (uint32_t)(((lane >> 4) & 1) * 8 + (lane & 7));
    const uint32_t tcb  = (uint32_t)(((lane >> 3) & 1) * 16);

    #pragma unroll
    for (int ks = 0; ks < 8; ks++) {
        uint32_t kb = (uint32_t)(ks * 32) + lcb;
        uint32_t ah[8];
        ldsm4(ah,     sQh + lrA * TS3 + kb);
        ldsm4(ah + 4, sQh + (lrA + 16) * TS3 + kb);
        uint32_t boff = ((uint32_t)(ks * 16) + trow) * TS3 + tcb;
        #pragma unroll
        for (int nb = 0; nb < 2; nb++) {
            uint32_t eb = (uint32_t)(wn * 64 + nb * 32);
            uint32_t bh[4];
            ldsm4t(bh, sMh + boff + eb);
            #pragma unroll
            for (int ma = 0; ma < 2; ma++) {
                mma_fp16(acc[ma][nb*2+0], ah + ma*4, bh[0], bh[2]);
                mma_fp16(acc[ma][nb*2+1], ah + ma*4, bh[1], bh[3]);
            }
        }
    }

    const float scale = 0.08838834764831845f;    // 128^-0.5
    const int g8 = lane >> 2;
    const int t4 = lane & 3;
    #pragma unroll
    for (int ma = 0; ma < 2; ma++) {
        int r = s0 + wm * 32 + ma * 16 + g8;
        #pragma unroll
        for (int na = 0; na < 4; na++) {
            int col = wn * 32 + na * 8 + t4 * 2;
            *(float2*)&out[((size_t)b * SEQ + r) * D + col] =
                make_float2(acc[ma][na][0] * scale, acc[ma][na][1] * scale);
            *(float2*)&out[((size_t)b * SEQ + r + 8) * D + col] =
                make_float2(acc[ma][na][2] * scale, acc[ma][na][3] * scale);
        }
    }
}

// ---------------------------------------------------------------------------
extern "C" void kernel_launch(void* const* d_in, const int* in_sizes, int n_in,
                              void* d_out, int out_size)
{
    const float* x  = (const float*)d_in[0];
    const float* Wq = (const float*)d_in[1];
    const float* bq = (const float*)d_in[2];
    const float* Wk = (const float*)d_in[3];
    const float* bk = (const float*)d_in[4];
    const float* Wv = (const float*)d_in[5];
    const float* bv = (const float*)d_in[6];
    float* out = (float*)d_out;

    static cudaStream_t s2 = nullptr;
    static cudaEvent_t evKV = nullptr, evQ = nullptr;
    if (s2 == nullptr) {
        cudaStreamCreateWithFlags(&s2, cudaStreamNonBlocking);
        cudaEventCreateWithFlags(&evKV, cudaEventDisableTiming);
        cudaEventCreateWithFlags(&evQ,  cudaEventDisableTiming);
        cudaFuncSetAttribute(kv_mma_kernel,
                             cudaFuncAttributeMaxDynamicSharedMemorySize, 2 * STG2);
        cudaFuncSetAttribute(q_mma_kernel,
                             cudaFuncAttributeMaxDynamicSharedMemorySize, 2 * STG2);
        cudaFuncSetAttribute(ktv_mma_kernel,
                             cudaFuncAttributeMaxDynamicSharedMemorySize, 2 * TILE3);
        cudaFuncSetAttribute(out_mma_kernel,
                             cudaFuncAttributeMaxDynamicSharedMemorySize, QTILE + TILE3);
    }

    // Main stream: cvt -> kv projection -> ktv -> reduce -> (join q) -> out.
    cvt_kernel<<<16768, 256>>>(x, Wq, Wk, Wv);
    kv_mma_kernel<<<dim3(ROWS / 128, 2), 256, 2 * STG2>>>(bk, bv);
    cudaEventRecord(evKV, 0);

    // Fork: q projection (512 threads, 16 warps) overlaps ktv+reduce.
    cudaStreamWaitEvent(s2, evKV, 0);
    q_mma_kernel<<<dim3(ROWS / 128), 512, 2 * STG2, s2>>>(bq);
    cudaEventRecord(evQ, s2);

    ktv_mma_kernel<<<dim3(TSPL, BATCH), 256, 2 * TILE3>>>();
    reduce_m_kernel<<<64, 256>>>();

    // Join and finish.
    cudaStreamWaitEvent(0, evQ, 0);
    out_mma_kernel<<<dim3(SEQ / 64, BATCH), 256, QTILE + TILE3>>>(out);
}

// round 16
// speedup vs baseline: 1.3380x; 1.0238x over previous
#include <cuda_runtime.h>
#include <cuda_fp16.h>
#include <cstdint>

#define D      128
#define DM     1024
#define BATCH  4
#define SEQ    4096
#define ROWS   (BATCH * SEQ)   // 16384
#define TSPL   16              // ktv split count
#define NCHQ   32              // fused kv K chunks of 32
#define NCH2   16              // q K chunks of 64

// Scratch (allocation-free rule: __device__ globals)
__device__ __half g_xh[(size_t)ROWS * DM];
__device__ __half g_wh[3 * D * DM];
__device__ __half g_qh[ROWS * D];
__device__ __half g_kh[ROWS * D];
__device__ __half g_vh[ROWS * D];
__device__ float  g_mpart[BATCH * TSPL * D * D];
__device__ __half g_mh[BATCH * D * D];

// ===========================================================================
// helpers (sm_80-era PTX: ldmatrix / mma.sync / cp.async)
// ===========================================================================
__device__ __forceinline__ uint32_t s2u(const void* p) {
    uint32_t a;
    asm("{ .reg .u64 t; cvta.to.shared.u64 t, %1; cvt.u32.u64 %0, t; }"
        : "=r"(a) : "l"(p));
    return a;
}
__device__ __forceinline__ void ldsm4(uint32_t* r, uint32_t addr) {
    asm volatile("ldmatrix.sync.aligned.m8n8.x4.shared.b16 {%0,%1,%2,%3}, [%4];"
                 : "=r"(r[0]), "=r"(r[1]), "=r"(r[2]), "=r"(r[3]) : "r"(addr));
}
__device__ __forceinline__ void ldsm4t(uint32_t* r, uint32_t addr) {
    asm volatile("ldmatrix.sync.aligned.m8n8.x4.trans.shared.b16 {%0,%1,%2,%3}, [%4];"
                 : "=r"(r[0]), "=r"(r[1]), "=r"(r[2]), "=r"(r[3]) : "r"(addr));
}
__device__ __forceinline__ void mma_fp16(float* d, const uint32_t* a,
                                         uint32_t b0, uint32_t b1) {
    asm volatile(
        "mma.sync.aligned.m16n8k16.row.col.f32.f16.f16.f32 "
        "{%0,%1,%2,%3}, {%4,%5,%6,%7}, {%8,%9}, {%0,%1,%2,%3};"
        : "+f"(d[0]), "+f"(d[1]), "+f"(d[2]), "+f"(d[3])
        : "r"(a[0]), "r"(a[1]), "r"(a[2]), "r"(a[3]), "r"(b0), "r"(b1));
}
__device__ __forceinline__ void cpa16(uint32_t dst, const void* src) {
    asm volatile("cp.async.cg.shared.global [%0], [%1], 16;" :: "r"(dst), "l"(src));
}
__device__ __forceinline__ uint32_t pk2(float a, float b) {
    __half2 h = __floats2half2_rn(a, b);
    return *(uint32_t*)&h;
}

// ===========================================================================
// Kernel 0: convert W -> fp16 (tiny: 384 blocks).
// ===========================================================================
__global__ __launch_bounds__(256) void cvt_w_kernel(
    const float* __restrict__ Wq, const float* __restrict__ Wk,
    const float* __restrict__ Wv)
{
    size_t j = ((size_t)blockIdx.x * 256 + threadIdx.x) * 4;
    if (j >= (size_t)3 * D * DM) return;
    size_t w = j >> 17;
    const float* src = (w == 0) ? Wq : (w == 1) ? Wk : Wv;
    size_t off = j & 131071;
    float4 v = *(const float4*)&src[off];
    *(uint32_t*)&g_wh[j]     = pk2(v.x, v.y);
    *(uint32_t*)&g_wh[j + 2] = pk2(v.z, v.w);
}

// ===========================================================================
// Kernel 1: KV projection with FUSED x fp32->fp16 conversion (R12 proven),
// plus xh WRITEBACK by the k-head CTAs (feeds the q projection).
// Per chunk (K=32): cp.async fp32 x tile (dbl-buf) + fp16 W tile (tri-buf);
// convert A32->A16 in smem (+store to g_xh if head==1); ldsm+mma.
// smem: A32 2x18432 + B 3x10240 + A16 10240 = 77824 B -> 2 CTAs/SM.
// ===========================================================================
#define TSA32 144                  // fp32 A row stride (128B data + 16 pad)
#define A32T  (128 * TSA32)        // 18432
#define TSB   80                   // fp16 row stride (64B data + 16 pad)
#define BT    (128 * TSB)          // 10240
#define OFF_B    (2 * A32T)        // 36864
#define OFF_A16  (OFF_B + 3 * BT)  // 67584
#define QF_SMEM  (OFF_A16 + BT)    // 77824

__global__ __launch_bounds__(256, 2) void kv_fused_kernel(
    const float* __restrict__ x,
    const float* __restrict__ bk, const float* __restrict__ bv)
{
    extern __shared__ char smem[];
    const uint32_t sb = s2u(smem);

    const int tid  = threadIdx.x;
    const int lane = tid & 31;
    const int wid  = tid >> 5;
    const int wm   = wid & 3;        // 32-row M block
    const int wn   = wid >> 2;       // 64-col N block
    const int head = 1 + blockIdx.y; // 1=k, 2=v
    const int row0 = blockIdx.x * 128;

    const float*  xg  = x + (size_t)row0 * DM;
    const __half* Bhg = g_wh + ((size_t)head << 17);
    const float* bias = (head == 1) ? bk : bv;
    __half* oh = (head == 1) ? g_kh : g_vh;
    const bool writeback = (head == 1);

    // A32 cp.async mapping: 128 rows x 8 16B-units = 1024 slots, 4 per thread.
    // B   cp.async mapping: 128 rows x 4 16B-units =  512 slots, 2 per thread.
    const int ar = tid >> 3, au = tid & 7;              // +i*32 rows
    const int br = tid >> 2, bu = tid & 3;              // +i*64 rows

    #define KVF_ISSUE(c) do {                                                  \
        uint32_t _a = sb + ((c) & 1) * A32T;                                    \
        uint32_t _bb = sb + OFF_B + ((c) % 3) * BT;                             \
        _Pragma("unroll")                                                       \
        for (int _i = 0; _i < 4; _i++) {                                        \
            int _r = ar + _i * 32;                                              \
            cpa16(_a + (uint32_t)(_r * TSA32 + au * 16),                        \
                  xg + (size_t)_r * DM + (c) * 32 + au * 4);                    \
        }                                                                       \
        _Pragma("unroll")                                                       \
        for (int _i = 0; _i < 2; _i++) {                                        \
            int _r = br + _i * 64;                                              \
            cpa16(_bb + (uint32_t)(_r * TSB + bu * 16),                         \
                  Bhg + (size_t)_r * DM + (c) * 32 + bu * 8);                   \
        }                                                                       \
    } while (0)

    float acc[2][8][4];
    #pragma unroll
    for (int i = 0; i < 2; i++)
        #pragma unroll
        for (int j = 0; j < 8; j++)
            #pragma unroll
            for (int q = 0; q < 4; q++) acc[i][j][q] = 0.0f;

    KVF_ISSUE(0);
    asm volatile("cp.async.commit_group;" ::: "memory");
    KVF_ISSUE(1);
    asm volatile("cp.async.commit_group;" ::: "memory");

    const uint32_t lrA = (uint32_t)(wm * 32 + (lane & 15));
    const uint32_t lcb = (uint32_t)((lane >> 4) << 4);

    for (int c = 0; c < NCHQ; c++) {
        asm volatile("cp.async.wait_group 1;" ::: "memory");
        __syncthreads();   // A32/B chunk c visible; prior chunk's ldsm done

        // Convert A32[c&1] -> A16 smem (+ writeback g_xh for the k head).
        {
            const char* a32 = smem + (c & 1) * A32T;
            #pragma unroll
            for (int i = 0; i < 4; i++) {
                int r = ar + i * 32;
                float4 v = *(const float4*)(a32 + r * TSA32 + au * 16);
                uint2 hp = make_uint2(pk2(v.x, v.y), pk2(v.z, v.w));
                *(uint2*)(smem + OFF_A16 + r * TSB + au * 8) = hp;
                if (writeback)
                    *(uint2*)&g_xh[(size_t)(row0 + r) * DM + c * 32 + au * 4] = hp;
            }
        }
        __syncthreads();   // A16 ready; A32[c&1] free for reuse

        if (c + 2 < NCHQ) KVF_ISSUE(c + 2);
        asm volatile("cp.async.commit_group;" ::: "memory");

        uint32_t bH = sb + OFF_B + (c % 3) * BT;
        uint32_t aH = sb + OFF_A16;

        #pragma unroll
        for (int ks = 0; ks < 2; ks++) {
            uint32_t kb = (uint32_t)(ks * 32) + lcb;
            uint32_t ah[8];
            ldsm4(ah,     aH + lrA * TSB + kb);
            ldsm4(ah + 4, aH + (lrA + 16) * TSB + kb);
            #pragma unroll
            for (int nb = 0; nb < 4; nb++) {
                uint32_t rb = (uint32_t)(wn * 64 + nb * 16 + (lane & 15));
                uint32_t bh[4];
                ldsm4(bh, bH + rb * TSB + kb);
                #pragma unroll
                for (int ma = 0; ma < 2; ma++) {
                    mma_fp16(acc[ma][nb*2+0], ah + ma*4, bh[0], bh[2]);
                    mma_fp16(acc[ma][nb*2+1], ah + ma*4, bh[1], bh[3]);
                }
            }
        }
    }

    // Epilogue: add bias, store fp16 hi.
    const int g8  = lane >> 2;
    const int t4  = lane & 3;
    #pragma unroll
    for (int ma = 0; ma < 2; ma++) {
        int r = row0 + wm * 32 + ma * 16 + g8;
        #pragma unroll
        for (int na = 0; na < 8; na++) {
            int col = wn * 64 + na * 8 + t4 * 2;
            float bx = __ldg(&bias[col]), by = __ldg(&bias[col + 1]);
            *(uint32_t*)&oh[(size_t)r * D + col] =
                pk2(acc[ma][na][0] + bx, acc[ma][na][1] + by);
            *(uint32_t*)&oh[(size_t)(r + 8) * D + col] =
                pk2(acc[ma][na][2] + bx, acc[ma][na][3] + by);
        }
    }
}

// ===========================================================================
// Kernel 1q: Q projection, 512 threads (16 warps), reads g_xh (R15 proven).
// CTA 128x128xK64 double buffered; warps 4M x 4N (warp 32x32). fp16-hi out.
// ===========================================================================
#define TS2   144                 // smem bytes per row (128 data + 16 pad)
#define TILE2 (128 * TS2)         // 18432
#define STG2  (2 * TILE2)         // 36864 per stage (Ah, Bh)

__global__ __launch_bounds__(512, 1) void q_mma_kernel(
    const float* __restrict__ bq)
{
    extern __shared__ char smem[];
    const uint32_t sb = s2u(smem);

    const int tid  = threadIdx.x;
    const int lane = tid & 31;
    const int wid  = tid >> 5;       // 0..15
    const int wm   = wid & 3;        // 32-row M block (4)
    const int wn   = wid >> 2;       // 32-col N block (4)
    const int row0 = blockIdx.x * 128;

    const __half* Ahg = g_xh + (size_t)row0 * DM;
    const __half* Bhg = g_wh;        // head 0 = q

    int cr[2], cu[2];
    #pragma unroll
    for (int i = 0; i < 2; i++) {
        int slot = tid + i * 512;
        cr[i] = slot >> 3;
        cu[i] = slot & 7;
    }

    #define QISSUE512(c) do {                                                  \
        uint32_t _b = sb + ((c) & 1) * STG2;                                   \
        _Pragma("unroll")                                                      \
        for (int _i = 0; _i < 2; _i++) {                                       \
            uint32_t _so = (uint32_t)(cr[_i] * TS2 + cu[_i] * 16);             \
            size_t _go = (size_t)cr[_i] * DM + (c) * 64 + cu[_i] * 8;          \
            cpa16(_b + _so,         Ahg + _go);                                \
            cpa16(_b + TILE2 + _so, Bhg + _go);                                \
        }                                                                      \
    } while (0)

    float acc[2][4][4];
    #pragma unroll
    for (int i = 0; i < 2; i++)
        #pragma unroll
        for (int j = 0; j < 4; j++)
            #pragma unroll
            for (int q = 0; q < 4; q++) acc[i][j][q] = 0.0f;

    QISSUE512(0);
    asm volatile("cp.async.commit_group;" ::: "memory");
    QISSUE512(1);
    asm volatile("cp.async.commit_group;" ::: "memory");

    const uint32_t lrA = (uint32_t)(wm * 32 + (lane & 15));
    const uint32_t lcb = (uint32_t)((lane >> 4) << 4);

    for (int c = 0; c < NCH2; c++) {
        asm volatile("cp.async.wait_group 1;" ::: "memory");
        __syncthreads();

        uint32_t base = sb + (c & 1) * STG2;
        uint32_t aH = base, bH = base + TILE2;

        #pragma unroll
        for (int ks = 0; ks < 4; ks++) {
            uint32_t kb = (uint32_t)(ks * 32) + lcb;
            uint32_t ah[8];
            ldsm4(ah,     aH + lrA * TS2 + kb);
            ldsm4(ah + 4, aH + (lrA + 16) * TS2 + kb);
            #pragma unroll
            for (int nb = 0; nb < 2; nb++) {
                uint32_t rb = (uint32_t)(wn * 32 + nb * 16 + (lane & 15));
                uint32_t bh[4];
                ldsm4(bh, bH + rb * TS2 + kb);
                #pragma unroll
                for (int ma = 0; ma < 2; ma++) {
                    mma_fp16(acc[ma][nb*2+0], ah + ma*4, bh[0], bh[2]);
                    mma_fp16(acc[ma][nb*2+1], ah + ma*4, bh[1], bh[3]);
                }
            }
        }
        __syncthreads();
        if (c + 2 < NCH2) QISSUE512(c + 2);
        asm volatile("cp.async.commit_group;" ::: "memory");
    }

    const int g8  = lane >> 2;
    const int t4  = lane & 3;
    #pragma unroll
    for (int ma = 0; ma < 2; ma++) {
        int r = row0 + wm * 32 + ma * 16 + g8;
        #pragma unroll
        for (int na = 0; na < 4; na++) {
            int col = wn * 32 + na * 8 + t4 * 2;
            float bx = __ldg(&bq[col]), by = __ldg(&bq[col + 1]);
            *(uint32_t*)&g_qh[(size_t)r * D + col] =
                pk2(acc[ma][na][0] + bx, acc[ma][na][1] + by);
            *(uint32_t*)&g_qh[(size_t)(r + 8) * D + col] =
                pk2(acc[ma][na][2] + bx, acc[ma][na][3] + by);
        }
    }
}

// ===========================================================================
// Kernel 2a: ktv partials on tensor cores, 1-term fp16.
// M_part[d,e] = sum_{t in split} kh[t,d] * vh[t,e]; 256 t-rows per CTA.
// ===========================================================================
#define TS3   272                 // 256 data + 16 pad
#define TILE3 (128 * TS3)         // 34816

__global__ __launch_bounds__(256) void ktv_mma_kernel()
{
    extern __shared__ char smem[];
    const uint32_t sb = s2u(smem);
    const uint32_t sKh = sb, sVh = sb + TILE3;

    const int tid  = threadIdx.x;
    const int lane = tid & 31;
    const int wid  = tid >> 5;
    const int wm   = wid & 3;        // d block (32)
    const int wn   = wid >> 2;       // e block (64)
    const int b    = blockIdx.y;
    const int t0   = blockIdx.x * 256;

    float acc[2][8][4];
    #pragma unroll
    for (int i = 0; i < 2; i++)
        #pragma unroll
        for (int j = 0; j < 8; j++)
            #pragma unroll
            for (int q = 0; q < 4; q++) acc[i][j][q] = 0.0f;

    const uint32_t trow = (uint32_t)(((lane >> 4) & 1) * 8 + (lane & 7));
    const uint32_t tcb  = (uint32_t)(((lane >> 3) & 1) * 16);

    for (int cc = 0; cc < 2; cc++) {
        const __half* khg = g_kh + ((size_t)b * SEQ + t0 + cc * 128) * D;
        const __half* vhg = g_vh + ((size_t)b * SEQ + t0 + cc * 128) * D;

        #pragma unroll
        for (int i = 0; i < 8; i++) {
            int slot = tid + i * 256;
            int r = slot >> 4, u = slot & 15;
            uint32_t so = (uint32_t)(r * TS3 + u * 16);
            size_t go = (size_t)r * D + u * 8;
            cpa16(sKh + so, khg + go);
            cpa16(sVh + so, vhg + go);
        }
        asm volatile("cp.async.commit_group;" ::: "memory");
        asm volatile("cp.async.wait_group 0;" ::: "memory");
        __syncthreads();

        #pragma unroll
        for (int ks = 0; ks < 8; ks++) {
            uint32_t aoff = ((uint32_t)(ks * 16) + trow) * TS3 + tcb;
            uint32_t ah[8];
            ldsm4t(ah,     sKh + aoff + wm * 64);
            ldsm4t(ah + 4, sKh + aoff + wm * 64 + 32);
            #pragma unroll
            for (int nb = 0; nb < 4; nb++) {
                uint32_t eb = (uint32_t)(wn * 128 + nb * 32);
                uint32_t bh[4];
                ldsm4t(bh, sVh + aoff + eb);
                #pragma unroll
                for (int ma = 0; ma < 2; ma++) {
                    mma_fp16(acc[ma][nb*2+0], ah + ma*4, bh[0], bh[2]);
                    mma_fp16(acc[ma][nb*2+1], ah + ma*4, bh[1], bh[3]);
                }
            }
        }
        __syncthreads();
    }

    float* outp = g_mpart + ((size_t)(b * TSPL + blockIdx.x) << 14);
    const int g8 = lane >> 2;
    const int t4 = lane & 3;
    #pragma unroll
    for (int ma = 0; ma < 2; ma++) {
        int r = wm * 32 + ma * 16 + g8;
        #pragma unroll
        for (int na = 0; na < 8; na++) {
            int col = wn * 64 + na * 8 + t4 * 2;
            *(float2*)&outp[(size_t)r * D + col] =
                make_float2(acc[ma][na][0], acc[ma][na][1]);
            *(float2*)&outp[(size_t)(r + 8) * D + col] =
                make_float2(acc[ma][na][2], acc[ma][na][3]);
        }
    }
}

// ===========================================================================
// Kernel 2b: reduce partials -> Mh fp16 (vectorized float4).
// ===========================================================================
__global__ __launch_bounds__(256) void reduce_m_kernel()
{
    int s  = blockIdx.x * 256 + threadIdx.x;     // 0..16383 (float4 slots)
    int b  = s >> 12;                            // 4096 slots per batch
    int sl = s & 4095;
    const float4* mp4 = (const float4*)g_mpart + ((size_t)b * TSPL << 12);
    float4 sum = make_float4(0.f, 0.f, 0.f, 0.f);
    #pragma unroll
    for (int p = 0; p < TSPL; p++) {
        float4 v = mp4[((size_t)p << 12) + sl];
        sum.x += v.x; sum.y += v.y; sum.z += v.z; sum.w += v.w;
    }
    int idx = s * 4;
    *(uint32_t*)&g_mh[idx]     = pk2(sum.x, sum.y);
    *(uint32_t*)&g_mh[idx + 2] = pk2(sum.z, sum.w);
}

// ===========================================================================
// Kernel 3: out = scale * q @ Mh, 1-term fp16, 64-row Q tiles (256 CTAs).
// A = qh [s][d] (non-trans); B = Mh [d][e] via ldmatrix.trans.
// Warps: 2M x 4N (warp 32x32).
// ===========================================================================
#define QTILE (64 * TS3)          // 17408

__global__ __launch_bounds__(256) void out_mma_kernel(float* __restrict__ out)
{
    extern __shared__ char smem[];
    const uint32_t sb = s2u(smem);
    const uint32_t sQh = sb, sMh = sb + QTILE;

    const int tid  = threadIdx.x;
    const int lane = tid & 31;
    const int wid  = tid >> 5;
    const int wm   = wid & 1;        // s block (32)
    const int wn   = wid >> 1;       // e block (32)
    const int b    = blockIdx.y;
    const int s0   = blockIdx.x * 64;

    const __half* qhg = g_qh + ((size_t)b * SEQ + s0) * D;
    const __half* mhg = g_mh + ((size_t)b << 14);

    #pragma unroll
    for (int i = 0; i < 4; i++) {
        int slot = tid + i * 256;
        int r = slot >> 4, u = slot & 15;
        cpa16(sQh + (uint32_t)(r * TS3 + u * 16), qhg + (size_t)r * D + u * 8);
    }
    #pragma unroll
    for (int i = 0; i < 8; i++) {
        int slot = tid + i * 256;
        int r = slot >> 4, u = slot & 15;
        cpa16(sMh + (uint32_t)(r * TS3 + u * 16), mhg + (size_t)r * D + u * 8);
    }
    asm volatile("cp.async.commit_group;" ::: "memory");
    asm volatile("cp.async.wait_group 0;" ::: "memory");
    __syncthreads();

    float acc[2][4][4];
    #pragma unroll
    for (int i = 0; i < 2; i++)
        #pragma unroll
        for (int j = 0; j < 4; j++)
            #pragma unroll
            for (int q = 0; q < 4; q++) acc[i][j][q] = 0.0f;

    const uint32_t lrA  = (uint32_t)(wm * 32 + (lane & 15));
    const uint32_t lcb  = (uint32_t)((lane >> 4) << 4);
    const uint32_t trow = (uint32_t)(((lane >> 4) & 1) * 8 + (lane & 7));
    const uint32_t tcb  = (uint32_t)(((lane >> 3) & 1) * 16);

    #pragma unroll
    for (int ks = 0; ks < 8; ks++) {
        uint32_t kb = (uint32_t)(ks * 32) + lcb;
        uint32_t ah[8];
        ldsm4(ah,     sQh + lrA * TS3 + kb);
        ldsm4(ah + 4, sQh + (lrA + 16) * TS3 + kb);
        uint32_t boff = ((uint32_t)(ks * 16) + trow) * TS3 + tcb;
        #pragma unroll
        for (int nb = 0; nb < 2; nb++) {
            uint32_t eb = (uint32_t)(wn * 64 + nb * 32);
            uint32_t bh[4];
            ldsm4t(bh, sMh + boff + eb);
            #pragma unroll
            for (int ma = 0; ma < 2; ma++) {
                mma_fp16(acc[ma][nb*2+0], ah + ma*4, bh[0], bh[2]);
                mma_fp16(acc[ma][nb*2+1], ah + ma*4, bh[1], bh[3]);
            }
        }
    }

    const float scale = 0.08838834764831845f;    // 128^-0.5
    const int g8 = lane >> 2;
    const int t4 = lane & 3;
    #pragma unroll
    for (int ma = 0; ma < 2; ma++) {
        int r = s0 + wm * 32 + ma * 16 + g8;
        #pragma unroll
        for (int na = 0; na < 4; na++) {
            int col = wn * 32 + na * 8 + t4 * 2;
            *(float2*)&out[((size_t)b * SEQ + r) * D + col] =
                make_float2(acc[ma][na][0] * scale, acc[ma][na][1] * scale);
            *(float2*)&out[((size_t)b * SEQ + r + 8) * D + col] =
                make_float2(acc[ma][na][2] * scale, acc[ma][na][3] * scale);
        }
    }
}

// ---------------------------------------------------------------------------
extern "C" void kernel_launch(void* const* d_in, const int* in_sizes, int n_in,
                              void* d_out, int out_size)
{
    const float* x  = (const float*)d_in[0];
    const float* Wq = (const float*)d_in[1];
    const float* bq = (const float*)d_in[2];
    const float* Wk = (const float*)d_in[3];
    const float* bk = (const float*)d_in[4];
    const float* Wv = (const float*)d_in[5];
    const float* bv = (const float*)d_in[6];
    float* out = (float*)d_out;

    static cudaStream_t s2 = nullptr;
    static cudaEvent_t evKV = nullptr, evQ = nullptr;
    if (s2 == nullptr) {
        cudaStreamCreateWithFlags(&s2, cudaStreamNonBlocking);
        cudaEventCreateWithFlags(&evKV, cudaEventDisableTiming);
        cudaEventCreateWithFlags(&evQ,  cudaEventDisableTiming);
        cudaFuncSetAttribute(kv_fused_kernel,
                             cudaFuncAttributeMaxDynamicSharedMemorySize, QF_SMEM);
        cudaFuncSetAttribute(q_mma_kernel,
                             cudaFuncAttributeMaxDynamicSharedMemorySize, 2 * STG2);
        cudaFuncSetAttribute(ktv_mma_kernel,
                             cudaFuncAttributeMaxDynamicSharedMemorySize, 2 * TILE3);
        cudaFuncSetAttribute(out_mma_kernel,
                             cudaFuncAttributeMaxDynamicSharedMemorySize, QTILE + TILE3);
    }

    // s0: W cvt (tiny) -> fused kv projection (converts x, writes g_xh).
    cvt_w_kernel<<<384, 256>>>(Wq, Wk, Wv);
    kv_fused_kernel<<<dim3(ROWS / 128, 2), 256, QF_SMEM>>>(x, bk, bv);
    cudaEventRecord(evKV, 0);

    // Fork: q projection (512 threads) overlaps ktv+reduce; g_xh ready via evKV.
    cudaStreamWaitEvent(s2, evKV, 0);
    q_mma_kernel<<<dim3(ROWS / 128), 512, 2 * STG2, s2>>>(bq);
    cudaEventRecord(evQ, s2);

    ktv_mma_kernel<<<dim3(TSPL, BATCH), 256, 2 * TILE3>>>();
    reduce_m_kernel<<<64, 256>>>();

    // Join and finish.
    cudaStreamWaitEvent(0, evQ, 0);
    out_mma_kernel<<<dim3(SEQ / 64, BATCH), 256, QTILE + TILE3>>>(out);
}